// round 15
// baseline (speedup 1.0000x reference)
#include <cuda_runtime.h>
#include <math.h>

// Problem shape (fixed by reference setup_inputs)
#define UU 2048
#define TT 512
#define QQ 10000
#define HH 128
#define UT (UU*TT)
#define CH2 8          // scan: time steps per lane (2 warps/user * 32 * 8 = 512)

#define TBLK 592       // table kernel blocks (4/SM)
#define NCHUNK 2500    // 8-pair chunks: 2500*8 = 20000 exactly

// Scratch (device globals: allocation-free, graph-capturable)
__device__ float  g_diff[QQ];
__device__ float  g_disc[QQ];
__device__ float2 g_tab[2*QQ];     // (mu, lmda) per (q, resp)

__device__ __forceinline__ float gelu_exact(float x) {
    return 0.5f * x * (1.0f + erff(x * 0.70710678118654752440f));
}
// single-MUFU reciprocal: used ONLY for uniform scaling (any value works as
// long as it multiplies every matrix entry identically).
__device__ __forceinline__ float frcp(float x) {
    float r; asm("rcp.approx.f32 %0, %1;" : "=f"(r) : "f"(x)); return r;
}

// ---------------------------------------------------------------------------
// Kernel 1 (fused sample + MLP table): resp = round(uniform) in {0,1}, so the
// MLP has only 2*QQ distinct inputs. 256 threads/block, two 128-thread halves,
// each half computes 4 pairs (2 q x 2 resp) per W2 pass. Chunk = 8 pairs:
// finer grid-stride granularity cuts tail imbalance (ceil/avg 1.42 -> 1.18).
// ---------------------------------------------------------------------------
__global__ void __launch_bounds__(256, 4) table_kernel(
        const float* __restrict__ dmu, const float* __restrict__ dlv,
        const float* __restrict__ cmu, const float* __restrict__ clv,
        const float* __restrict__ ed,  const float* __restrict__ ec,
        const float* __restrict__ W1, const float* __restrict__ b1,
        const float* __restrict__ W2, const float* __restrict__ b2,
        const float* __restrict__ W3, const float* __restrict__ b3) {
    const int tid  = threadIdx.x;
    const int half = tid >> 7;          // 0 or 1
    const int j    = tid & 127;         // channel
    const int wwarp = (tid >> 5) & 3;   // warp within half
    const int lane  = tid & 31;

    // ---- folded sample pass (first 40 blocks cover QQ) ----
    int gid = blockIdx.x * 256 + tid;
    if (gid < QQ) {
        g_diff[gid] = fmaf(__expf(0.5f * dlv[gid]), ed[gid], dmu[gid]);
        g_disc[gid] = fmaf(__expf(0.5f * clv[gid]), ec[gid], cmu[gid]);
    }

    __shared__ __align__(16) float h1s[8][HH];    // 8 pairs per chunk
    __shared__ float s_red[8][2][4];              // [pair][comp][warp]

    const float w1a = __ldg(&W1[j]);
    const float w1b = __ldg(&W1[HH + j]);
    const float w1c = __ldg(&W1[2*HH + j]);
    const float b1j = __ldg(&b1[j]);
    const float b2j = __ldg(&b2[j]);
    const float w3a = __ldg(&W3[2*j + 0]);
    const float w3b = __ldg(&W3[2*j + 1]);
    const float b30 = __ldg(&b3[0]);
    const float b31 = __ldg(&b3[1]);

    for (int c = blockIdx.x; c < NCHUNK; c += TBLK) {
        const int pbase = c * 8;             // 8 pairs; all < 2*QQ by range
        const int qbase = c * 4 + half * 2;  // this half's 2 q's

        // ---- layer 1: 2 q's x {resp=0,1} -> 4 h rows for this half ----
#pragma unroll
        for (int g = 0; g < 2; ++g) {
            int q = qbase + g;
            float td = fmaf(__expf(0.5f * __ldg(&dlv[q])), __ldg(&ed[q]), __ldg(&dmu[q]));
            float tc = fmaf(__expf(0.5f * __ldg(&clv[q])), __ldg(&ec[q]), __ldg(&cmu[q]));
            float pre0 = fmaf(td, w1a, fmaf(tc, w1b, b1j));   // resp = 0
            float pre1 = pre0 + w1c;                          // resp = 1
            h1s[half*4 + 2*g + 0][j] = gelu_exact(pre0);
            h1s[half*4 + 2*g + 1][j] = gelu_exact(pre1);
        }
        __syncthreads();

        // ---- layer 2: one W2 pass, 2 accumulator banks per pair ----
        float accA[4], accB[4];
#pragma unroll
        for (int p = 0; p < 4; ++p) { accA[p] = b2j; accB[p] = 0.f; }
#pragma unroll 4
        for (int kc = 0; kc < 32; ++kc) {
            int k = kc * 4;
            float w0 = __ldg(&W2[(k+0)*HH + j]);
            float w1 = __ldg(&W2[(k+1)*HH + j]);
            float w2 = __ldg(&W2[(k+2)*HH + j]);
            float w3 = __ldg(&W2[(k+3)*HH + j]);
#pragma unroll
            for (int p = 0; p < 4; ++p) {
                float4 v = *reinterpret_cast<const float4*>(&h1s[half*4 + p][k]);
                accA[p] = fmaf(v.x, w0, fmaf(v.z, w2, accA[p]));
                accB[p] = fmaf(v.y, w1, fmaf(v.w, w3, accB[p]));
            }
        }

        // ---- layer 3: 8 values per lane (4 pairs x {m0,m1}) ----
        float val[8];
#pragma unroll
        for (int p = 0; p < 4; ++p) {
            float hv = gelu_exact(accA[p] + accB[p]);
            val[2*p + 0] = hv * w3a;
            val[2*p + 1] = hv * w3b;
        }
        // Multi-value butterfly: stages o=16,8,4 halve the value count; after
        // them lane L owns value (L>>2)&7; stages o=2,1 finish. 9 shuffles.
        {
            bool b16 = (lane & 16) != 0;
#pragma unroll
            for (int i = 0; i < 4; ++i) {
                float send = b16 ? val[i] : val[4+i];
                float r = __shfl_xor_sync(0xffffffffu, send, 16);
                val[i] = (b16 ? val[4+i] : val[i]) + r;
            }
            bool b8 = (lane & 8) != 0;
#pragma unroll
            for (int i = 0; i < 2; ++i) {
                float send = b8 ? val[i] : val[2+i];
                float r = __shfl_xor_sync(0xffffffffu, send, 8);
                val[i] = (b8 ? val[2+i] : val[i]) + r;
            }
            bool b4 = (lane & 4) != 0;
            {
                float send = b4 ? val[0] : val[1];
                float r = __shfl_xor_sync(0xffffffffu, send, 4);
                val[0] = (b4 ? val[1] : val[0]) + r;
            }
            val[0] += __shfl_xor_sync(0xffffffffu, val[0], 2);
            val[0] += __shfl_xor_sync(0xffffffffu, val[0], 1);
        }
        if ((lane & 3) == 0) {
            int v = lane >> 2;              // owned value index: p*2 + comp
            s_red[half*4 + (v >> 1)][v & 1][wwarp] = val[0];
        }
        __syncthreads();

        if (tid < 8) {                      // one thread finalizes each pair
            int pair = pbase + tid;
            float mu = b30 + ((s_red[tid][0][0] + s_red[tid][0][1])
                            + (s_red[tid][0][2] + s_red[tid][0][3]));
            float p1 = b31 + ((s_red[tid][1][0] + s_red[tid][1][1])
                            + (s_red[tid][1][2] + s_red[tid][1][3]));
            g_tab[pair] = make_float2(mu, fminf(__expf(-p1), 1e32f));
        }
        __syncthreads();
    }
}

// ---------------------------------------------------------------------------
// Kernel 2 (fused): per-user scans, TWO warps per user. Warp w covers t in
// [w*256,(w+1)*256); lane k owns CH2=8 steps. Cross-warp stitch via smem.
// Warp-scan stages carry UNNORMALIZED composites (growth <= 2x/stage from
// chunk-normalized inputs, <= 32x total: no overflow) — per-stage divides
// deleted. Pure-scaling reciprocals use single-MUFU rcp.approx.
// ---------------------------------------------------------------------------
__global__ void __launch_bounds__(256) fused_scan_kernel(
        const int*   __restrict__ mask,
        const int*   __restrict__ q_id,
        const float* __restrict__ resp,
        const float* __restrict__ eps_ab,
        float*       __restrict__ out) {
    const int tid = threadIdx.x;
    const int uu  = tid >> 6;            // user slot in block (0..3)
    const int u   = blockIdx.x * 4 + uu;
    const int w   = (tid >> 5) & 1;      // half index (0 = early t, 1 = late t)
    const int k   = tid & 31;
    const int base = u * TT + w * 256 + k * CH2;

    __shared__ float sT[4][7];   // upper-half backward total per user
    __shared__ float sF[4][2];   // lower-half forward total per user

    // ---- preprocess 8 trials -> l (sign-encoded mask), lm ----
    float l[CH2], lm[CH2];
#pragma unroll
    for (int v = 0; v < 2; ++v) {
        int4   mk = reinterpret_cast<const int4*>(mask + base)[v];
        int4   q  = reinterpret_cast<const int4*>(q_id + base)[v];
        float4 r  = reinterpret_cast<const float4*>(resp + base)[v];
        int   mkv[4] = {mk.x, mk.y, mk.z, mk.w};
        int   qv[4]  = {q.x, q.y, q.z, q.w};
        float rv[4]  = {r.x, r.y, r.z, r.w};
#pragma unroll
        for (int s = 0; s < 4; ++s) {
            int i = v*4 + s;
            float2 ml = g_tab[(qv[s] << 1) | (rv[s] > 0.5f ? 1 : 0)];
            bool m = (mkv[s] != 0);
            l[i]  = m ? ml.y : -1.0f;     // l >= 0 always when unmasked
            lm[i] = ml.y * ml.x;          // unused when masked
        }
    }

    // ---- backward: per-lane chunk matrix over CH2 steps ----
    float A11 = 1.f, A12 = 0.f, A21 = 0.f, A22 = 1.f;
    float C1 = 0.f, C2 = 0.f, WC = 1.f;
#pragma unroll
    for (int i = CH2 - 1; i >= 0; --i) {
        if (l[i] >= 0.f) {
            float li = l[i];
            float s  = frcp(1.0f + li);           // uniform scaling only
            float n11 = (A11 + li * A21) * s;
            float n12 = (A12 + li * A22) * s;
            float n21 = n11 + A21 * s;
            float n22 = n12 + A22 * s;
            float nc1 = fmaf(lm[i], A21, C1) * s;
            float nc2 = fmaf(lm[i], A22, C2) * s;
            A11 = n11; A12 = n12; A21 = n21; A22 = n22;
            C1 = nc1; C2 = nc2; WC *= s;
        }
    }
    {
        float s = frcp(A22);                      // uniform scaling only
        A11 *= s; A12 *= s; A21 *= s; A22 *= s;
        C1 *= s; C2 *= s; WC *= s;
    }

    // ---- warp suffix scan, UNNORMALIZED (Z = A*Y; zc = C*y + WC*yc) ----
#pragma unroll
    for (int off = 1; off < 32; off <<= 1) {
        float y11 = __shfl_down_sync(0xffffffffu, A11, off);
        float y12 = __shfl_down_sync(0xffffffffu, A12, off);
        float y21 = __shfl_down_sync(0xffffffffu, A21, off);
        float y22 = __shfl_down_sync(0xffffffffu, A22, off);
        float yc1 = __shfl_down_sync(0xffffffffu, C1,  off);
        float yc2 = __shfl_down_sync(0xffffffffu, C2,  off);
        float ywc = __shfl_down_sync(0xffffffffu, WC,  off);
        if (k + off < 32) {
            float z11 = fmaf(A11, y11, A12 * y21);
            float z12 = fmaf(A11, y12, A12 * y22);
            float z21 = fmaf(A21, y11, A22 * y21);
            float z22 = fmaf(A21, y12, A22 * y22);
            float zc1 = fmaf(C1, y11, fmaf(C2, y21, WC * yc1));
            float zc2 = fmaf(C1, y12, fmaf(C2, y22, WC * yc2));
            float zwc = WC * ywc;
            A11 = z11; A12 = z12; A21 = z21; A22 = z22;
            C1 = zc1;  C2 = zc2;  WC = zwc;
        }
    }

    // upper warp's lane 0 holds the late-half total; renormalize for stitch
    if (w == 1 && k == 0) {
        float s = frcp(A22);
        sT[uu][0] = A11*s; sT[uu][1] = A12*s; sT[uu][2] = A21*s;
        sT[uu][3] = A22*s; sT[uu][4] = C1*s;  sT[uu][5] = C2*s;
        sT[uu][6] = WC*s;
    }

    // full exclusive suffix E per lane (identity at lane 31)
    float E11 = __shfl_down_sync(0xffffffffu, A11, 1);
    float E12 = __shfl_down_sync(0xffffffffu, A12, 1);
    float E21 = __shfl_down_sync(0xffffffffu, A21, 1);
    float E22 = __shfl_down_sync(0xffffffffu, A22, 1);
    float Ec1 = __shfl_down_sync(0xffffffffu, C1,  1);
    float Ec2 = __shfl_down_sync(0xffffffffu, C2,  1);
    float Ewc = __shfl_down_sync(0xffffffffu, WC,  1);
    if (k == 31) { E11 = 1.f; E12 = 0.f; E21 = 0.f; E22 = 1.f;
                   Ec1 = 0.f; Ec2 = 0.f; Ewc = 1.f; }
    __syncthreads();

    float a, ab;
    if (w == 0) {
        // compose Z = E * T (E newer/earlier-t, T = late-half total)
        float t12 = sT[uu][1], t22 = sT[uu][3], tc2 = sT[uu][5];
        float z12 = fmaf(E11, t12, E12 * t22);
        float z22 = fmaf(E21, t12, E22 * t22);
        float zc2 = fmaf(Ec1, t12, fmaf(Ec2, t22, Ewc * tc2));
        a  = z12 / z22;
        ab = zc2 / z22;
    } else {
        a  = E12 / E22;
        ab = Ec2 / E22;
    }

    // ---- backward replay, emitting forward coefficients directly ----
    // inv = 1/(1+l+a_pre); bet = (lm+ab_pre)*inv + sqrt(1-a_pre)*e;
    // ab_new = (lm+ab_pre)*inv, a_new = (l+a_pre)*inv.
    float inv[CH2], bet[CH2];
#pragma unroll
    for (int v = 1; v >= 0; --v) {
        float4 e = reinterpret_cast<const float4*>(eps_ab + base)[v];
        float ev[4] = {e.x, e.y, e.z, e.w};
#pragma unroll
        for (int s = 3; s >= 0; --s) {
            int i = v*4 + s;
            if (l[i] >= 0.f) {
                float d   = l[i] + a;
                float iv  = __fdividef(1.0f, 1.0f + d);
                float nab = (lm[i] + ab) * iv;
                inv[i] = iv;
                bet[i] = fmaf(sqrtf(fmaxf(0.0f, 1.0f - a)), ev[s], nab);
                a  = d * iv;
                ab = nab;
            } else {
                inv[i] = 1.0f; bet[i] = 0.0f;
            }
        }
    }

    // ---- per-lane affine compose (t ascending) ----
    float alC = 1.f, beC = 0.f;
#pragma unroll
    for (int i = 0; i < CH2; ++i) {
        beC = fmaf(inv[i], beC, bet[i]);
        alC *= inv[i];
    }

    // ---- warp inclusive prefix scan of affine pairs ----
#pragma unroll
    for (int off = 1; off < 32; off <<= 1) {
        float ya = __shfl_up_sync(0xffffffffu, alC, off);
        float yb = __shfl_up_sync(0xffffffffu, beC, off);
        if (k >= off) {
            beC = fmaf(alC, yb, beC);
            alC *= ya;
        }
    }

    // lower warp's lane 31 holds the early-half affine total
    if (w == 0 && k == 31) { sF[uu][0] = alC; sF[uu][1] = beC; }

    // exclusive prefix per lane
    float alE = __shfl_up_sync(0xffffffffu, alC, 1);
    float beE = __shfl_up_sync(0xffffffffu, beC, 1);
    if (k == 0) { alE = 1.f; beE = 0.f; }
    __syncthreads();

    float th;
    if (w == 1) {
        float beT = sF[uu][1];
        th = fmaf(alE, beT, beE);     // apply early-half total first (th0 = 0)
    } else {
        th = beE;
    }

    // ---- forward replay + streaming float4 outputs (q_id reloaded, L1) ----
#pragma unroll
    for (int g = 0; g < 2; ++g) {
        int4 q = reinterpret_cast<const int4*>(q_id + base)[g];
        int qv[4] = {q.x, q.y, q.z, q.w};
        float4 lof, aof;
#pragma unroll
        for (int s = 0; s < 4; ++s) {
            int i = 4*g + s;
            th = fmaf(th, inv[i], bet[i]);     // identity when masked
            float dc = g_disc[qv[s]];
            float lv = dc * (th - g_diff[qv[s]]);
            if (s == 0) { lof.x = lv; aof.x = th; }
            else if (s == 1) { lof.y = lv; aof.y = th; }
            else if (s == 2) { lof.z = lv; aof.z = th; }
            else { lof.w = lv; aof.w = th; }
        }
        reinterpret_cast<float4*>(out + base)[g] = lof;
        reinterpret_cast<float4*>(out + UT + base)[g] = aof;
    }
}

// ---------------------------------------------------------------------------
// Launch
// ---------------------------------------------------------------------------
extern "C" void kernel_launch(void* const* d_in, const int* in_sizes, int n_in,
                              void* d_out, int out_size) {
    const int*   mask   = (const int*)  d_in[0];
    const int*   q_id   = (const int*)  d_in[1];
    const float* resp   = (const float*)d_in[2];
    const float* dmu    = (const float*)d_in[3];
    const float* dlv    = (const float*)d_in[4];
    const float* cmu    = (const float*)d_in[5];
    const float* clv    = (const float*)d_in[6];
    const float* W1     = (const float*)d_in[7];
    const float* b1     = (const float*)d_in[8];
    const float* W2     = (const float*)d_in[9];
    const float* b2     = (const float*)d_in[10];
    const float* W3     = (const float*)d_in[11];
    const float* b3     = (const float*)d_in[12];
    const float* ed     = (const float*)d_in[13];
    const float* ec     = (const float*)d_in[14];
    const float* eps_ab = (const float*)d_in[15];
    float* out = (float*)d_out;

    table_kernel<<<TBLK, 256>>>(dmu, dlv, cmu, clv, ed, ec,
                                W1, b1, W2, b2, W3, b3);
    fused_scan_kernel<<<UU / 4, 256>>>(mask, q_id, resp, eps_ab, out);
}

// round 16
// speedup vs baseline: 1.1373x; 1.1373x over previous
#include <cuda_runtime.h>
#include <math.h>

// Problem shape (fixed by reference setup_inputs)
#define UU 2048
#define TT 512
#define QQ 10000
#define HH 128
#define UT (UU*TT)
#define CHS 4          // scan: steps per lane (4 warps/user * 32 * 4 = 512)

#define TBLK 592       // table kernel blocks (4/SM)
#define NCHUNK 1250    // 16-pair chunks: 1250*16 = 20000 exactly

// Scratch (device globals: allocation-free, graph-capturable)
__device__ float  g_diff[QQ];
__device__ float  g_disc[QQ];
__device__ float2 g_tab[2*QQ];     // (mu, lmda) per (q, resp)

__device__ __forceinline__ float gelu_exact(float x) {
    return 0.5f * x * (1.0f + erff(x * 0.70710678118654752440f));
}
// single-MUFU reciprocal: used ONLY for uniform scaling of homogeneous
// matrices (any scale works as long as it's applied to every entry).
__device__ __forceinline__ float frcp(float x) {
    float r; asm("rcp.approx.f32 %0, %1;" : "=f"(r) : "f"(x)); return r;
}

// ---------------------------------------------------------------------------
// Kernel 1 (fused sample + MLP table) — R14 version (known 33 us):
// 16-pair chunks, two 128-thread halves x 8 pairs per W2 pass, banked
// accumulators, grid-stride over exactly NCHUNK chunks.
// ---------------------------------------------------------------------------
__global__ void __launch_bounds__(256, 4) table_kernel(
        const float* __restrict__ dmu, const float* __restrict__ dlv,
        const float* __restrict__ cmu, const float* __restrict__ clv,
        const float* __restrict__ ed,  const float* __restrict__ ec,
        const float* __restrict__ W1, const float* __restrict__ b1,
        const float* __restrict__ W2, const float* __restrict__ b2,
        const float* __restrict__ W3, const float* __restrict__ b3) {
    const int tid  = threadIdx.x;
    const int half = tid >> 7;          // 0 or 1
    const int j    = tid & 127;         // channel
    const int wwarp = (tid >> 5) & 3;   // warp within half
    const int lane  = tid & 31;

    // ---- folded sample pass (first 40 blocks cover QQ) ----
    int gid = blockIdx.x * 256 + tid;
    if (gid < QQ) {
        g_diff[gid] = fmaf(__expf(0.5f * dlv[gid]), ed[gid], dmu[gid]);
        g_disc[gid] = fmaf(__expf(0.5f * clv[gid]), ec[gid], cmu[gid]);
    }

    __shared__ __align__(16) float h1s[16][HH];   // 16 pairs per chunk
    __shared__ float s_red[16][2][4];             // [pair][comp][warp]

    const float w1a = __ldg(&W1[j]);
    const float w1b = __ldg(&W1[HH + j]);
    const float w1c = __ldg(&W1[2*HH + j]);
    const float b1j = __ldg(&b1[j]);
    const float b2j = __ldg(&b2[j]);
    const float w3a = __ldg(&W3[2*j + 0]);
    const float w3b = __ldg(&W3[2*j + 1]);
    const float b30 = __ldg(&b3[0]);
    const float b31 = __ldg(&b3[1]);

    for (int c = blockIdx.x; c < NCHUNK; c += TBLK) {
        const int pbase = c * 16;            // 16 pairs; all < 2*QQ by range
        const int qbase = c * 8 + half * 4;  // this half's 4 q's

        // ---- layer 1: 4 q's x {resp=0,1} -> 8 h rows for this half ----
#pragma unroll
        for (int g = 0; g < 4; ++g) {
            int q = qbase + g;
            float td = fmaf(__expf(0.5f * __ldg(&dlv[q])), __ldg(&ed[q]), __ldg(&dmu[q]));
            float tc = fmaf(__expf(0.5f * __ldg(&clv[q])), __ldg(&ec[q]), __ldg(&cmu[q]));
            float pre0 = fmaf(td, w1a, fmaf(tc, w1b, b1j));   // resp = 0
            float pre1 = pre0 + w1c;                          // resp = 1
            h1s[half*8 + 2*g + 0][j] = gelu_exact(pre0);
            h1s[half*8 + 2*g + 1][j] = gelu_exact(pre1);
        }
        __syncthreads();

        // ---- layer 2: one W2 pass, 2 accumulator banks per pair ----
        float accA[8], accB[8];
#pragma unroll
        for (int p = 0; p < 8; ++p) { accA[p] = b2j; accB[p] = 0.f; }
#pragma unroll 4
        for (int kc = 0; kc < 32; ++kc) {
            int k = kc * 4;
            float w0 = __ldg(&W2[(k+0)*HH + j]);
            float w1 = __ldg(&W2[(k+1)*HH + j]);
            float w2 = __ldg(&W2[(k+2)*HH + j]);
            float w3 = __ldg(&W2[(k+3)*HH + j]);
#pragma unroll
            for (int p = 0; p < 8; ++p) {
                float4 v = *reinterpret_cast<const float4*>(&h1s[half*8 + p][k]);
                accA[p] = fmaf(v.x, w0, fmaf(v.z, w2, accA[p]));
                accB[p] = fmaf(v.y, w1, fmaf(v.w, w3, accB[p]));
            }
        }

        // ---- layer 3: 16 values per lane (8 pairs x {m0,m1}) ----
        float val[16];
#pragma unroll
        for (int p = 0; p < 8; ++p) {
            float hv = gelu_exact(accA[p] + accB[p]);
            val[2*p + 0] = hv * w3a;
            val[2*p + 1] = hv * w3b;
        }
        // Multi-value butterfly: stages o=16,8,4,2; lane L ends owning value
        // (L>>1)&15; stage o=1 finishes. 15 shuffles.
        {
            bool b16 = (lane & 16) != 0;
#pragma unroll
            for (int i = 0; i < 8; ++i) {
                float send = b16 ? val[i] : val[8+i];
                float r = __shfl_xor_sync(0xffffffffu, send, 16);
                val[i] = (b16 ? val[8+i] : val[i]) + r;
            }
            bool b8 = (lane & 8) != 0;
#pragma unroll
            for (int i = 0; i < 4; ++i) {
                float send = b8 ? val[i] : val[4+i];
                float r = __shfl_xor_sync(0xffffffffu, send, 8);
                val[i] = (b8 ? val[4+i] : val[i]) + r;
            }
            bool b4 = (lane & 4) != 0;
#pragma unroll
            for (int i = 0; i < 2; ++i) {
                float send = b4 ? val[i] : val[2+i];
                float r = __shfl_xor_sync(0xffffffffu, send, 4);
                val[i] = (b4 ? val[2+i] : val[i]) + r;
            }
            bool b2v = (lane & 2) != 0;
            {
                float send = b2v ? val[0] : val[1];
                float r = __shfl_xor_sync(0xffffffffu, send, 2);
                val[0] = (b2v ? val[1] : val[0]) + r;
            }
            val[0] += __shfl_xor_sync(0xffffffffu, val[0], 1);
        }
        if ((lane & 1) == 0) {
            int v = (lane >> 1) & 15;       // owned value index: p*2 + comp
            s_red[half*8 + (v >> 1)][v & 1][wwarp] = val[0];
        }
        __syncthreads();

        if (tid < 16) {                     // one thread finalizes each pair
            int pair = pbase + tid;
            float mu = b30 + ((s_red[tid][0][0] + s_red[tid][0][1])
                            + (s_red[tid][0][2] + s_red[tid][0][3]));
            float p1 = b31 + ((s_red[tid][1][0] + s_red[tid][1][1])
                            + (s_red[tid][1][2] + s_red[tid][1][3]));
            g_tab[pair] = make_float2(mu, fminf(__expf(-p1), 1e32f));
        }
        __syncthreads();
    }
}

// ---------------------------------------------------------------------------
// Kernel 2 (fused): per-user scans with FOUR warps per user (8192 warps,
// occ ~60%). Warp w covers t in [w*128,(w+1)*128); lane k owns CHS=4 steps.
// Each warp's normalized total goes to smem; lanes fold their within-warp
// exclusive suffix with the later warps' totals (backward) / earlier warps'
// affine totals (forward). Warp-scan stages are unnormalized (inputs have
// A22=1, growth <= 2x/stage: no overflow).
// ---------------------------------------------------------------------------
__global__ void __launch_bounds__(256) fused_scan_kernel(
        const int*   __restrict__ mask,
        const int*   __restrict__ q_id,
        const float* __restrict__ resp,
        const float* __restrict__ eps_ab,
        float*       __restrict__ out) {
    const int tid = threadIdx.x;
    const int uu  = tid >> 7;            // user slot in block (0..1)
    const int u   = blockIdx.x * 2 + uu;
    const int w   = (tid >> 5) & 3;      // quarter index (0 = earliest t)
    const int k   = tid & 31;
    const int base = u * TT + w * 128 + k * CHS;

    __shared__ float sTB[2][4][7];   // per-warp backward totals (normalized)
    __shared__ float sFA[2][4][2];   // per-warp forward affine totals

    // ---- load 4 trials -> l (sign-encoded mask), lm ----
    int4   mk = *reinterpret_cast<const int4*>(mask + base);
    int4   qv = *reinterpret_cast<const int4*>(q_id + base);
    float4 rv = *reinterpret_cast<const float4*>(resp + base);
    float4 ev = *reinterpret_cast<const float4*>(eps_ab + base);
    int   mka[4] = {mk.x, mk.y, mk.z, mk.w};
    int   qa[4]  = {qv.x, qv.y, qv.z, qv.w};
    float ra[4]  = {rv.x, rv.y, rv.z, rv.w};
    float ea[4]  = {ev.x, ev.y, ev.z, ev.w};

    float l[CHS], lm[CHS];
#pragma unroll
    for (int i = 0; i < CHS; ++i) {
        float2 ml = g_tab[(qa[i] << 1) | (ra[i] > 0.5f ? 1 : 0)];
        l[i]  = (mka[i] != 0) ? ml.y : -1.0f;   // l >= 0 always when unmasked
        lm[i] = ml.y * ml.x;
    }

    // ---- backward: per-lane chunk matrix over CHS steps (descending) ----
    float A11 = 1.f, A12 = 0.f, A21 = 0.f, A22 = 1.f;
    float C1 = 0.f, C2 = 0.f, WC = 1.f;
#pragma unroll
    for (int i = CHS - 1; i >= 0; --i) {
        if (l[i] >= 0.f) {
            float li = l[i];
            float s  = frcp(1.0f + li);           // uniform scaling only
            float n11 = (A11 + li * A21) * s;
            float n12 = (A12 + li * A22) * s;
            float n21 = n11 + A21 * s;
            float n22 = n12 + A22 * s;
            float nc1 = fmaf(lm[i], A21, C1) * s;
            float nc2 = fmaf(lm[i], A22, C2) * s;
            A11 = n11; A12 = n12; A21 = n21; A22 = n22;
            C1 = nc1; C2 = nc2; WC *= s;
        }
    }
    {
        float s = frcp(A22);                      // uniform scaling only
        A11 *= s; A12 *= s; A21 *= s; A22 *= s;
        C1 *= s; C2 *= s; WC *= s;
    }

    // ---- warp suffix scan, unnormalized (Z = A*Y; zc = C*y + WC*yc) ----
#pragma unroll
    for (int off = 1; off < 32; off <<= 1) {
        float y11 = __shfl_down_sync(0xffffffffu, A11, off);
        float y12 = __shfl_down_sync(0xffffffffu, A12, off);
        float y21 = __shfl_down_sync(0xffffffffu, A21, off);
        float y22 = __shfl_down_sync(0xffffffffu, A22, off);
        float yc1 = __shfl_down_sync(0xffffffffu, C1,  off);
        float yc2 = __shfl_down_sync(0xffffffffu, C2,  off);
        float ywc = __shfl_down_sync(0xffffffffu, WC,  off);
        if (k + off < 32) {
            float z11 = fmaf(A11, y11, A12 * y21);
            float z12 = fmaf(A11, y12, A12 * y22);
            float z21 = fmaf(A21, y11, A22 * y21);
            float z22 = fmaf(A21, y12, A22 * y22);
            float zc1 = fmaf(C1, y11, fmaf(C2, y21, WC * yc1));
            float zc2 = fmaf(C1, y12, fmaf(C2, y22, WC * yc2));
            float zwc = WC * ywc;
            A11 = z11; A12 = z12; A21 = z21; A22 = z22;
            C1 = zc1;  C2 = zc2;  WC = zwc;
        }
    }

    // lane 0 holds this warp's total composite; store normalized
    if (k == 0) {
        float s = frcp(A22);
        sTB[uu][w][0] = A11*s; sTB[uu][w][1] = A12*s; sTB[uu][w][2] = A21*s;
        sTB[uu][w][3] = A22*s; sTB[uu][w][4] = C1*s;  sTB[uu][w][5] = C2*s;
        sTB[uu][w][6] = WC*s;
    }

    // within-warp exclusive suffix E per lane (identity at lane 31)
    float E11 = __shfl_down_sync(0xffffffffu, A11, 1);
    float E12 = __shfl_down_sync(0xffffffffu, A12, 1);
    float E21 = __shfl_down_sync(0xffffffffu, A21, 1);
    float E22 = __shfl_down_sync(0xffffffffu, A22, 1);
    float Ec1 = __shfl_down_sync(0xffffffffu, C1,  1);
    float Ec2 = __shfl_down_sync(0xffffffffu, C2,  1);
    float Ewc = __shfl_down_sync(0xffffffffu, WC,  1);
    if (k == 31) { E11 = 1.f; E12 = 0.f; E21 = 0.f; E22 = 1.f;
                   Ec1 = 0.f; Ec2 = 0.f; Ewc = 1.f; }
    __syncthreads();

    // fold later warps' totals: E = ((E ∘ T_{w+1}) ∘ T_{w+2}) ∘ T_{w+3}
    for (int ww = w + 1; ww < 4; ++ww) {
        float t11 = sTB[uu][ww][0], t12 = sTB[uu][ww][1];
        float t21 = sTB[uu][ww][2], t22 = sTB[uu][ww][3];
        float tc1 = sTB[uu][ww][4], tc2 = sTB[uu][ww][5];
        float twc = sTB[uu][ww][6];
        float z11 = fmaf(E11, t11, E12 * t21);
        float z12 = fmaf(E11, t12, E12 * t22);
        float z21 = fmaf(E21, t11, E22 * t21);
        float z22 = fmaf(E21, t12, E22 * t22);
        float zc1 = fmaf(Ec1, t11, fmaf(Ec2, t21, Ewc * tc1));
        float zc2 = fmaf(Ec1, t12, fmaf(Ec2, t22, Ewc * tc2));
        float zwc = Ewc * twc;
        E11 = z11; E12 = z12; E21 = z21; E22 = z22;
        Ec1 = zc1; Ec2 = zc2; Ewc = zwc;
    }
    float a  = E12 / E22;
    float ab = Ec2 / E22;

    // ---- backward replay, emitting forward coefficients directly ----
    float inv[CHS], bet[CHS];
#pragma unroll
    for (int i = CHS - 1; i >= 0; --i) {
        if (l[i] >= 0.f) {
            float d   = l[i] + a;
            float iv  = __fdividef(1.0f, 1.0f + d);
            float nab = (lm[i] + ab) * iv;
            inv[i] = iv;
            bet[i] = fmaf(sqrtf(fmaxf(0.0f, 1.0f - a)), ea[i], nab);
            a  = d * iv;
            ab = nab;
        } else {
            inv[i] = 1.0f; bet[i] = 0.0f;
        }
    }

    // ---- per-lane affine compose (t ascending) ----
    float alC = 1.f, beC = 0.f;
#pragma unroll
    for (int i = 0; i < CHS; ++i) {
        beC = fmaf(inv[i], beC, bet[i]);
        alC *= inv[i];
    }

    // ---- warp inclusive prefix scan of affine pairs ----
#pragma unroll
    for (int off = 1; off < 32; off <<= 1) {
        float ya = __shfl_up_sync(0xffffffffu, alC, off);
        float yb = __shfl_up_sync(0xffffffffu, beC, off);
        if (k >= off) {
            beC = fmaf(alC, yb, beC);
            alC *= ya;
        }
    }
    if (k == 31) { sFA[uu][w][0] = alC; sFA[uu][w][1] = beC; }

    // exclusive prefix per lane
    float alE = __shfl_up_sync(0xffffffffu, alC, 1);
    float beE = __shfl_up_sync(0xffffffffu, beC, 1);
    if (k == 0) { alE = 1.f; beE = 0.f; }
    __syncthreads();

    // fold earlier warps' affine totals onto th0 = 0
    float v = 0.f;
    for (int ww = 0; ww < w; ++ww)
        v = fmaf(sFA[uu][ww][0], v, sFA[uu][ww][1]);
    float th = fmaf(alE, v, beE);

    // ---- forward replay + float4 outputs ----
    float4 lof, aof;
#pragma unroll
    for (int i = 0; i < CHS; ++i) {
        th = fmaf(th, inv[i], bet[i]);       // identity when masked
        float dc = g_disc[qa[i]];
        float lv = dc * (th - g_diff[qa[i]]);
        if (i == 0) { lof.x = lv; aof.x = th; }
        else if (i == 1) { lof.y = lv; aof.y = th; }
        else if (i == 2) { lof.z = lv; aof.z = th; }
        else { lof.w = lv; aof.w = th; }
    }
    *reinterpret_cast<float4*>(out + base)      = lof;
    *reinterpret_cast<float4*>(out + UT + base) = aof;
}

// ---------------------------------------------------------------------------
// Launch
// ---------------------------------------------------------------------------
extern "C" void kernel_launch(void* const* d_in, const int* in_sizes, int n_in,
                              void* d_out, int out_size) {
    const int*   mask   = (const int*)  d_in[0];
    const int*   q_id   = (const int*)  d_in[1];
    const float* resp   = (const float*)d_in[2];
    const float* dmu    = (const float*)d_in[3];
    const float* dlv    = (const float*)d_in[4];
    const float* cmu    = (const float*)d_in[5];
    const float* clv    = (const float*)d_in[6];
    const float* W1     = (const float*)d_in[7];
    const float* b1     = (const float*)d_in[8];
    const float* W2     = (const float*)d_in[9];
    const float* b2     = (const float*)d_in[10];
    const float* W3     = (const float*)d_in[11];
    const float* b3     = (const float*)d_in[12];
    const float* ed     = (const float*)d_in[13];
    const float* ec     = (const float*)d_in[14];
    const float* eps_ab = (const float*)d_in[15];
    float* out = (float*)d_out;

    table_kernel<<<TBLK, 256>>>(dmu, dlv, cmu, clv, ed, ec,
                                W1, b1, W2, b2, W3, b3);
    fused_scan_kernel<<<UU / 2, 256>>>(mask, q_id, resp, eps_ab, out);
}

// round 17
// speedup vs baseline: 1.1428x; 1.0048x over previous
#include <cuda_runtime.h>
#include <math.h>

// Problem shape (fixed by reference setup_inputs)
#define UU 2048
#define TT 512
#define QQ 10000
#define HH 128
#define UT (UU*TT)
#define CHS 4          // scan: steps per lane (4 warps/user * 32 * 4 = 512)

#define TBLK 592       // table kernel blocks (4/SM)
#define NCHUNK 1250    // 16-pair chunks: 1250*16 = 20000 exactly

// Scratch (device global: allocation-free, graph-capturable)
// g_tab[pair] = (mu, lmda, disc, diff) for pair = (q<<1)|resp
__device__ float4 g_tab[2*QQ];

__device__ __forceinline__ float gelu_exact(float x) {
    return 0.5f * x * (1.0f + erff(x * 0.70710678118654752440f));
}
// single-MUFU reciprocal: used ONLY for uniform scaling of homogeneous
// matrices (any scale works as long as it's applied to every entry).
__device__ __forceinline__ float frcp(float x) {
    float r; asm("rcp.approx.f32 %0, %1;" : "=f"(r) : "f"(x)); return r;
}

// ---------------------------------------------------------------------------
// Kernel 1 (MLP table): resp = round(uniform) in {0,1}, so the MLP has only
// 2*QQ distinct inputs. 16-pair chunks, two 128-thread halves x 8 pairs per
// W2 pass, banked accumulators. Emits float4 (mu, lmda, disc, diff) so the
// scan needs ONE scattered gather per trial.
// ---------------------------------------------------------------------------
__global__ void __launch_bounds__(256, 4) table_kernel(
        const float* __restrict__ dmu, const float* __restrict__ dlv,
        const float* __restrict__ cmu, const float* __restrict__ clv,
        const float* __restrict__ ed,  const float* __restrict__ ec,
        const float* __restrict__ W1, const float* __restrict__ b1,
        const float* __restrict__ W2, const float* __restrict__ b2,
        const float* __restrict__ W3, const float* __restrict__ b3) {
    const int tid  = threadIdx.x;
    const int half = tid >> 7;          // 0 or 1
    const int j    = tid & 127;         // channel
    const int wwarp = (tid >> 5) & 3;   // warp within half
    const int lane  = tid & 31;

    __shared__ __align__(16) float h1s[16][HH];   // 16 pairs per chunk
    __shared__ float s_red[16][2][4];             // [pair][comp][warp]
    __shared__ float2 s_tdtc[8];                  // (diff, disc) per q in chunk

    const float w1a = __ldg(&W1[j]);
    const float w1b = __ldg(&W1[HH + j]);
    const float w1c = __ldg(&W1[2*HH + j]);
    const float b1j = __ldg(&b1[j]);
    const float b2j = __ldg(&b2[j]);
    const float w3a = __ldg(&W3[2*j + 0]);
    const float w3b = __ldg(&W3[2*j + 1]);
    const float b30 = __ldg(&b3[0]);
    const float b31 = __ldg(&b3[1]);

    for (int c = blockIdx.x; c < NCHUNK; c += TBLK) {
        const int pbase = c * 16;            // 16 pairs; all < 2*QQ by range
        const int qbase = c * 8 + half * 4;  // this half's 4 q's

        // ---- layer 1: 4 q's x {resp=0,1} -> 8 h rows for this half ----
#pragma unroll
        for (int g = 0; g < 4; ++g) {
            int q = qbase + g;
            float td = fmaf(__expf(0.5f * __ldg(&dlv[q])), __ldg(&ed[q]), __ldg(&dmu[q]));
            float tc = fmaf(__expf(0.5f * __ldg(&clv[q])), __ldg(&ec[q]), __ldg(&cmu[q]));
            if (j == 0) s_tdtc[half*4 + g] = make_float2(td, tc);
            float pre0 = fmaf(td, w1a, fmaf(tc, w1b, b1j));   // resp = 0
            float pre1 = pre0 + w1c;                          // resp = 1
            h1s[half*8 + 2*g + 0][j] = gelu_exact(pre0);
            h1s[half*8 + 2*g + 1][j] = gelu_exact(pre1);
        }
        __syncthreads();

        // ---- layer 2: one W2 pass, 2 accumulator banks per pair ----
        float accA[8], accB[8];
#pragma unroll
        for (int p = 0; p < 8; ++p) { accA[p] = b2j; accB[p] = 0.f; }
#pragma unroll 4
        for (int kc = 0; kc < 32; ++kc) {
            int k = kc * 4;
            float w0 = __ldg(&W2[(k+0)*HH + j]);
            float w1 = __ldg(&W2[(k+1)*HH + j]);
            float w2 = __ldg(&W2[(k+2)*HH + j]);
            float w3 = __ldg(&W2[(k+3)*HH + j]);
#pragma unroll
            for (int p = 0; p < 8; ++p) {
                float4 v = *reinterpret_cast<const float4*>(&h1s[half*8 + p][k]);
                accA[p] = fmaf(v.x, w0, fmaf(v.z, w2, accA[p]));
                accB[p] = fmaf(v.y, w1, fmaf(v.w, w3, accB[p]));
            }
        }

        // ---- layer 3: 16 values per lane (8 pairs x {m0,m1}) ----
        float val[16];
#pragma unroll
        for (int p = 0; p < 8; ++p) {
            float hv = gelu_exact(accA[p] + accB[p]);
            val[2*p + 0] = hv * w3a;
            val[2*p + 1] = hv * w3b;
        }
        // Multi-value butterfly: stages o=16,8,4,2; lane L ends owning value
        // (L>>1)&15; stage o=1 finishes. 15 shuffles.
        {
            bool b16 = (lane & 16) != 0;
#pragma unroll
            for (int i = 0; i < 8; ++i) {
                float send = b16 ? val[i] : val[8+i];
                float r = __shfl_xor_sync(0xffffffffu, send, 16);
                val[i] = (b16 ? val[8+i] : val[i]) + r;
            }
            bool b8 = (lane & 8) != 0;
#pragma unroll
            for (int i = 0; i < 4; ++i) {
                float send = b8 ? val[i] : val[4+i];
                float r = __shfl_xor_sync(0xffffffffu, send, 8);
                val[i] = (b8 ? val[4+i] : val[i]) + r;
            }
            bool b4 = (lane & 4) != 0;
#pragma unroll
            for (int i = 0; i < 2; ++i) {
                float send = b4 ? val[i] : val[2+i];
                float r = __shfl_xor_sync(0xffffffffu, send, 4);
                val[i] = (b4 ? val[2+i] : val[i]) + r;
            }
            bool b2v = (lane & 2) != 0;
            {
                float send = b2v ? val[0] : val[1];
                float r = __shfl_xor_sync(0xffffffffu, send, 2);
                val[0] = (b2v ? val[1] : val[0]) + r;
            }
            val[0] += __shfl_xor_sync(0xffffffffu, val[0], 1);
        }
        if ((lane & 1) == 0) {
            int v = (lane >> 1) & 15;       // owned value index: p*2 + comp
            s_red[half*8 + (v >> 1)][v & 1][wwarp] = val[0];
        }
        __syncthreads();

        if (tid < 16) {                     // one thread finalizes each pair
            int pair = pbase + tid;
            float mu = b30 + ((s_red[tid][0][0] + s_red[tid][0][1])
                            + (s_red[tid][0][2] + s_red[tid][0][3]));
            float p1 = b31 + ((s_red[tid][1][0] + s_red[tid][1][1])
                            + (s_red[tid][1][2] + s_red[tid][1][3]));
            float2 tdtc = s_tdtc[tid >> 1];
            g_tab[pair] = make_float4(mu, fminf(__expf(-p1), 1e32f),
                                      tdtc.y, tdtc.x);   // (mu, lmda, disc, diff)
        }
        __syncthreads();
    }
}

// ---------------------------------------------------------------------------
// Kernel 2 (fused): per-user scans with FOUR warps per user (8192 warps).
// Warp w covers t in [w*128,(w+1)*128); lane k owns CHS=4 steps. ONE
// scattered float4 gather per step supplies (mu, lmda, disc, diff).
// Warp-scan stages are unnormalized (inputs have A22=1, growth <= 2x/stage).
// ---------------------------------------------------------------------------
__global__ void __launch_bounds__(256) fused_scan_kernel(
        const int*   __restrict__ mask,
        const int*   __restrict__ q_id,
        const float* __restrict__ resp,
        const float* __restrict__ eps_ab,
        float*       __restrict__ out) {
    const int tid = threadIdx.x;
    const int uu  = tid >> 7;            // user slot in block (0..1)
    const int u   = blockIdx.x * 2 + uu;
    const int w   = (tid >> 5) & 3;      // quarter index (0 = earliest t)
    const int k   = tid & 31;
    const int base = u * TT + w * 128 + k * CHS;

    __shared__ float sTB[2][4][7];   // per-warp backward totals (normalized)
    __shared__ float sFA[2][4][2];   // per-warp forward affine totals

    // ---- load 4 trials; one scattered float4 gather per step ----
    int4   mk = *reinterpret_cast<const int4*>(mask + base);
    int4   qv = *reinterpret_cast<const int4*>(q_id + base);
    float4 rv = *reinterpret_cast<const float4*>(resp + base);
    float4 ev = *reinterpret_cast<const float4*>(eps_ab + base);
    int   mka[4] = {mk.x, mk.y, mk.z, mk.w};
    int   qa[4]  = {qv.x, qv.y, qv.z, qv.w};
    float ra[4]  = {rv.x, rv.y, rv.z, rv.w};
    float ea[4]  = {ev.x, ev.y, ev.z, ev.w};

    float l[CHS], lm[CHS], dd[CHS], dp[CHS];
#pragma unroll
    for (int i = 0; i < CHS; ++i) {
        float4 tb = g_tab[(qa[i] << 1) | (ra[i] > 0.5f ? 1 : 0)];
        l[i]  = (mka[i] != 0) ? tb.y : -1.0f;   // l >= 0 always when unmasked
        lm[i] = tb.y * tb.x;
        dd[i] = tb.z;            // disc
        dp[i] = tb.z * tb.w;     // disc * diff
    }

    // ---- backward: per-lane chunk matrix over CHS steps (descending) ----
    float A11 = 1.f, A12 = 0.f, A21 = 0.f, A22 = 1.f;
    float C1 = 0.f, C2 = 0.f, WC = 1.f;
#pragma unroll
    for (int i = CHS - 1; i >= 0; --i) {
        if (l[i] >= 0.f) {
            float li = l[i];
            float s  = frcp(1.0f + li);           // uniform scaling only
            float n11 = (A11 + li * A21) * s;
            float n12 = (A12 + li * A22) * s;
            float n21 = n11 + A21 * s;
            float n22 = n12 + A22 * s;
            float nc1 = fmaf(lm[i], A21, C1) * s;
            float nc2 = fmaf(lm[i], A22, C2) * s;
            A11 = n11; A12 = n12; A21 = n21; A22 = n22;
            C1 = nc1; C2 = nc2; WC *= s;
        }
    }
    {
        float s = frcp(A22);                      // uniform scaling only
        A11 *= s; A12 *= s; A21 *= s; A22 *= s;
        C1 *= s; C2 *= s; WC *= s;
    }

    // ---- warp suffix scan, unnormalized (Z = A*Y; zc = C*y + WC*yc) ----
#pragma unroll
    for (int off = 1; off < 32; off <<= 1) {
        float y11 = __shfl_down_sync(0xffffffffu, A11, off);
        float y12 = __shfl_down_sync(0xffffffffu, A12, off);
        float y21 = __shfl_down_sync(0xffffffffu, A21, off);
        float y22 = __shfl_down_sync(0xffffffffu, A22, off);
        float yc1 = __shfl_down_sync(0xffffffffu, C1,  off);
        float yc2 = __shfl_down_sync(0xffffffffu, C2,  off);
        float ywc = __shfl_down_sync(0xffffffffu, WC,  off);
        if (k + off < 32) {
            float z11 = fmaf(A11, y11, A12 * y21);
            float z12 = fmaf(A11, y12, A12 * y22);
            float z21 = fmaf(A21, y11, A22 * y21);
            float z22 = fmaf(A21, y12, A22 * y22);
            float zc1 = fmaf(C1, y11, fmaf(C2, y21, WC * yc1));
            float zc2 = fmaf(C1, y12, fmaf(C2, y22, WC * yc2));
            float zwc = WC * ywc;
            A11 = z11; A12 = z12; A21 = z21; A22 = z22;
            C1 = zc1;  C2 = zc2;  WC = zwc;
        }
    }

    // lane 0 holds this warp's total composite; store normalized
    if (k == 0) {
        float s = frcp(A22);
        sTB[uu][w][0] = A11*s; sTB[uu][w][1] = A12*s; sTB[uu][w][2] = A21*s;
        sTB[uu][w][3] = A22*s; sTB[uu][w][4] = C1*s;  sTB[uu][w][5] = C2*s;
        sTB[uu][w][6] = WC*s;
    }

    // within-warp exclusive suffix E per lane (identity at lane 31)
    float E11 = __shfl_down_sync(0xffffffffu, A11, 1);
    float E12 = __shfl_down_sync(0xffffffffu, A12, 1);
    float E21 = __shfl_down_sync(0xffffffffu, A21, 1);
    float E22 = __shfl_down_sync(0xffffffffu, A22, 1);
    float Ec1 = __shfl_down_sync(0xffffffffu, C1,  1);
    float Ec2 = __shfl_down_sync(0xffffffffu, C2,  1);
    float Ewc = __shfl_down_sync(0xffffffffu, WC,  1);
    if (k == 31) { E11 = 1.f; E12 = 0.f; E21 = 0.f; E22 = 1.f;
                   Ec1 = 0.f; Ec2 = 0.f; Ewc = 1.f; }
    __syncthreads();

    // fold later warps' totals: E = ((E ∘ T_{w+1}) ∘ T_{w+2}) ∘ T_{w+3}
    for (int ww = w + 1; ww < 4; ++ww) {
        float t11 = sTB[uu][ww][0], t12 = sTB[uu][ww][1];
        float t21 = sTB[uu][ww][2], t22 = sTB[uu][ww][3];
        float tc1 = sTB[uu][ww][4], tc2 = sTB[uu][ww][5];
        float twc = sTB[uu][ww][6];
        float z11 = fmaf(E11, t11, E12 * t21);
        float z12 = fmaf(E11, t12, E12 * t22);
        float z21 = fmaf(E21, t11, E22 * t21);
        float z22 = fmaf(E21, t12, E22 * t22);
        float zc1 = fmaf(Ec1, t11, fmaf(Ec2, t21, Ewc * tc1));
        float zc2 = fmaf(Ec1, t12, fmaf(Ec2, t22, Ewc * tc2));
        float zwc = Ewc * twc;
        E11 = z11; E12 = z12; E21 = z21; E22 = z22;
        Ec1 = zc1; Ec2 = zc2; Ewc = zwc;
    }
    float a  = E12 / E22;
    float ab = Ec2 / E22;

    // ---- backward replay, emitting forward coefficients directly ----
    float inv[CHS], bet[CHS];
#pragma unroll
    for (int i = CHS - 1; i >= 0; --i) {
        if (l[i] >= 0.f) {
            float d   = l[i] + a;
            float iv  = __fdividef(1.0f, 1.0f + d);
            float nab = (lm[i] + ab) * iv;
            inv[i] = iv;
            bet[i] = fmaf(sqrtf(fmaxf(0.0f, 1.0f - a)), ea[i], nab);
            a  = d * iv;
            ab = nab;
        } else {
            inv[i] = 1.0f; bet[i] = 0.0f;
        }
    }

    // ---- per-lane affine compose (t ascending) ----
    float alC = 1.f, beC = 0.f;
#pragma unroll
    for (int i = 0; i < CHS; ++i) {
        beC = fmaf(inv[i], beC, bet[i]);
        alC *= inv[i];
    }

    // ---- warp inclusive prefix scan of affine pairs ----
#pragma unroll
    for (int off = 1; off < 32; off <<= 1) {
        float ya = __shfl_up_sync(0xffffffffu, alC, off);
        float yb = __shfl_up_sync(0xffffffffu, beC, off);
        if (k >= off) {
            beC = fmaf(alC, yb, beC);
            alC *= ya;
        }
    }
    if (k == 31) { sFA[uu][w][0] = alC; sFA[uu][w][1] = beC; }

    // exclusive prefix per lane
    float alE = __shfl_up_sync(0xffffffffu, alC, 1);
    float beE = __shfl_up_sync(0xffffffffu, beC, 1);
    if (k == 0) { alE = 1.f; beE = 0.f; }
    __syncthreads();

    // fold earlier warps' affine totals onto th0 = 0
    float v = 0.f;
    for (int ww = 0; ww < w; ++ww)
        v = fmaf(sFA[uu][ww][0], v, sFA[uu][ww][1]);
    float th = fmaf(alE, v, beE);

    // ---- forward replay + float4 outputs (no reloads) ----
    float4 lof, aof;
#pragma unroll
    for (int i = 0; i < CHS; ++i) {
        th = fmaf(th, inv[i], bet[i]);       // identity when masked
        float lv = fmaf(dd[i], th, -dp[i]);  // disc*(ability - diff)
        if (i == 0) { lof.x = lv; aof.x = th; }
        else if (i == 1) { lof.y = lv; aof.y = th; }
        else if (i == 2) { lof.z = lv; aof.z = th; }
        else { lof.w = lv; aof.w = th; }
    }
    *reinterpret_cast<float4*>(out + base)      = lof;
    *reinterpret_cast<float4*>(out + UT + base) = aof;
}

// ---------------------------------------------------------------------------
// Launch
// ---------------------------------------------------------------------------
extern "C" void kernel_launch(void* const* d_in, const int* in_sizes, int n_in,
                              void* d_out, int out_size) {
    const int*   mask   = (const int*)  d_in[0];
    const int*   q_id   = (const int*)  d_in[1];
    const float* resp   = (const float*)d_in[2];
    const float* dmu    = (const float*)d_in[3];
    const float* dlv    = (const float*)d_in[4];
    const float* cmu    = (const float*)d_in[5];
    const float* clv    = (const float*)d_in[6];
    const float* W1     = (const float*)d_in[7];
    const float* b1     = (const float*)d_in[8];
    const float* W2     = (const float*)d_in[9];
    const float* b2     = (const float*)d_in[10];
    const float* W3     = (const float*)d_in[11];
    const float* b3     = (const float*)d_in[12];
    const float* ed     = (const float*)d_in[13];
    const float* ec     = (const float*)d_in[14];
    const float* eps_ab = (const float*)d_in[15];
    float* out = (float*)d_out;

    table_kernel<<<TBLK, 256>>>(dmu, dlv, cmu, clv, ed, ec,
                                W1, b1, W2, b2, W3, b3);
    fused_scan_kernel<<<UU / 2, 256>>>(mask, q_id, resp, eps_ab, out);
}